// round 12
// baseline (speedup 1.0000x reference)
#include <cuda_runtime.h>
#include <cuda_fp16.h>
#include <cstdint>

// ---------------------------------------------------------------------------
// 6 chained GEMMs C = A @ W^T + b via single-pass fp16 mma.sync HMMA.
// R12: single-barrier software pipeline. Per K-chunk:
//   cp.async.wait_group 1 -> __syncthreads -> issue load(c+2) -> compute(c)
// (wait BEFORE the barrier: wait_group only orders the issuing thread's own
// groups; the barrier then publishes everyone's completed G_c writes, and
// simultaneously proves slot (c-1)%3 is no longer being read.)
// 3 smem slots, 2 groups in flight, 1 barrier/chunk (was 2).
// CTA 128x128, 8 warps of 64x32, 2 CTAs/SM, BKC=64.
// Host: conv launches reordered so launch #6 (ncu -s 5) is gemm1p.
// ---------------------------------------------------------------------------

#define BM 128
#define BN 128
#define BKC 64
#define ROWB 144u           // 64 fp16 = 128B data + 16B pad (9 x 16B units)
#define TILE_B 18432u       // 128 rows * 144B
#define STG_BYTES 36864u    // A + W (2 tiles)
#define NSTG 3
#define SMEM_SZ (NSTG * STG_BYTES)

static const int T_TOK = 16384, HID = 2048, IMM = 4096;

// ---- scratch (__device__ globals; allocation-guard-safe) ----
__device__ __half g_wh[150994944];           // all weights fp16 (302 MB)
__device__ __half g_aA[67108864];            // 16384 x 4096 activations
__device__ __half g_aB[33554432];            // 16384 x 2048 activations

__device__ __forceinline__ uint32_t smem_u32(const void* p) {
    uint32_t a;
    asm("{ .reg .u64 t; cvta.to.shared.u64 t, %1; cvt.u32.u64 %0, t; }" : "=r"(a) : "l"(p));
    return a;
}
__device__ __forceinline__ void cp16(uint32_t dst, const void* src) {
    asm volatile("cp.async.cg.shared.global [%0], [%1], 16;" :: "r"(dst), "l"(src));
}
__device__ __forceinline__ void cp_commit() {
    asm volatile("cp.async.commit_group;" ::: "memory");
}
__device__ __forceinline__ void cp_wait1() {
    asm volatile("cp.async.wait_group 1;" ::: "memory");
}
__device__ __forceinline__ void ldsm4(uint32_t* r, uint32_t a) {
    asm volatile("ldmatrix.sync.aligned.m8n8.x4.shared.b16 {%0,%1,%2,%3}, [%4];"
                 : "=r"(r[0]), "=r"(r[1]), "=r"(r[2]), "=r"(r[3]) : "r"(a));
}
__device__ __forceinline__ void mma16816(float* d, const uint32_t* a, const uint32_t* b) {
    asm volatile("mma.sync.aligned.m16n8k16.row.col.f32.f16.f16.f32 "
                 "{%0,%1,%2,%3}, {%4,%5,%6,%7}, {%8,%9}, {%0,%1,%2,%3};"
                 : "+f"(d[0]), "+f"(d[1]), "+f"(d[2]), "+f"(d[3])
                 : "r"(a[0]), "r"(a[1]), "r"(a[2]), "r"(a[3]), "r"(b[0]), "r"(b[1]));
}

// ---- fp32 -> fp16 ----
__global__ void conv_h(const float4* __restrict__ in, __half* __restrict__ o, int n4)
{
    int i = blockIdx.x * blockDim.x + threadIdx.x;
    if (i >= n4) return;
    float4 v = in[i];
    uint2 p;
    p.x = (uint32_t)__half_as_ushort(__float2half(v.x))
        | ((uint32_t)__half_as_ushort(__float2half(v.y)) << 16);
    p.y = (uint32_t)__half_as_ushort(__float2half(v.z))
        | ((uint32_t)__half_as_ushort(__float2half(v.w)) << 16);
    ((uint2*)o)[i] = p;
}

// C[M,N] = A[M,K] @ W[N,K]^T + bias; grouped via blockIdx.z.
__global__ void __launch_bounds__(256, 2)
gemm1p(const __half* __restrict__ A, const __half* __restrict__ W,
       const float* __restrict__ bias, float* __restrict__ Cf,
       __half* __restrict__ Ch,
       int M, int N, int K, int wantF32)
{
    extern __shared__ char smem[];
    const uint32_t sb = smem_u32(smem);

    const int tid  = threadIdx.x;
    const int lane = tid & 31;
    const int warp = tid >> 5;
    const int wm   = warp >> 2;   // 0..1 -> m offset 64
    const int wn   = warp & 3;    // 0..3 -> n offset 32
    const size_t g = blockIdx.z;
    const int n0 = blockIdx.x * BN;
    const int m0 = blockIdx.y * BM;

    const __half* Ag = A + g * (size_t)M * K + (size_t)m0 * K;
    const __half* Wg = W + g * (size_t)N * K + (size_t)n0 * K;

    // one stage = 2 tiles x 128 rows x 8 units = 2048 cp16; 8 per thread
    auto load_stage = [&](int c, int s) {
        const uint32_t st = sb + (uint32_t)s * STG_BYTES;
        const size_t kof = (size_t)c * BKC;
        #pragma unroll
        for (int i = 0; i < 8; i++) {
            int l = i * 256 + tid;
            const __half* src;
            uint32_t base;
            int t;
            if (i < 4) { t = l;        src = Ag; base = st; }
            else       { t = l - 1024; src = Wg; base = st + TILE_B; }
            int row = t >> 3, c8 = t & 7;
            cp16(base + (uint32_t)row * ROWB + (uint32_t)c8 * 16,
                 src + (size_t)row * K + kof + c8 * 8);
        }
        cp_commit();
    };

    float acc[4][4][4];
    #pragma unroll
    for (int mf = 0; mf < 4; mf++)
        #pragma unroll
        for (int nf = 0; nf < 4; nf++)
            #pragma unroll
            for (int q = 0; q < 4; q++) acc[mf][nf][q] = 0.f;

    const int KC = K / BKC;
    load_stage(0, 0);
    load_stage(1, 1);

    // ldmatrix base addresses (non-trans; both operands K-major)
    const uint32_t aRow = (uint32_t)(wm * 64 + (lane & 15)) * ROWB + (uint32_t)(lane >> 4) * 16;
    const uint32_t bRow = (uint32_t)(wn * 32 + ((lane >> 4) << 3) + (lane & 7)) * ROWB
                        + (uint32_t)((lane >> 3) & 1) * 16;

    int s = 0;                      // read slot = c % 3
    int sw = 2;                     // write slot = (c + 2) % 3
    for (int c = 0; c < KC; c++) {
        const uint32_t st = sb + (uint32_t)s * STG_BYTES;

        cp_wait1();                 // own G_c complete (2 groups may stay in flight)
        __syncthreads();            // publish everyone's G_c; slot sw free to overwrite

        if (c + 2 < KC) load_stage(c + 2, sw);
        else cp_commit();           // keep group-count invariant

        #pragma unroll
        for (int ks = 0; ks < 4; ks++) {
            const uint32_t ko = (uint32_t)ks * 32;  // 16 fp16 = 32B
            uint32_t a[4][4], b[2][4];
            #pragma unroll
            for (int mf = 0; mf < 4; mf++)
                ldsm4(a[mf], st + aRow + (uint32_t)mf * 16 * ROWB + ko);
            #pragma unroll
            for (int nf2 = 0; nf2 < 2; nf2++)
                ldsm4(b[nf2], st + TILE_B + bRow + (uint32_t)nf2 * 16 * ROWB + ko);
            #pragma unroll
            for (int mf = 0; mf < 4; mf++)
                #pragma unroll
                for (int nf2 = 0; nf2 < 2; nf2++) {
                    mma16816(acc[mf][2 * nf2],     a[mf], &b[nf2][0]);
                    mma16816(acc[mf][2 * nf2 + 1], a[mf], &b[nf2][2]);
                }
        }

        s  = (s  + 1 == NSTG) ? 0 : s  + 1;
        sw = (sw + 1 == NSTG) ? 0 : sw + 1;
    }

    // ---- epilogue ----
    const size_t co = g * (size_t)M * N;
    const float* bp = bias + g * N;
    #pragma unroll
    for (int mf = 0; mf < 4; mf++) {
        const int r0 = m0 + wm * 64 + mf * 16 + (lane >> 2);
        #pragma unroll
        for (int nf = 0; nf < 4; nf++) {
            const int cb = n0 + wn * 32 + nf * 8 + (lane & 3) * 2;
            const float b0 = bp[cb], b1 = bp[cb + 1];
            const float y00 = acc[mf][nf][0] + b0, y01 = acc[mf][nf][1] + b1;
            const float y10 = acc[mf][nf][2] + b0, y11 = acc[mf][nf][3] + b1;
            const size_t o0 = co + (size_t)r0 * N + cb;
            const size_t o1 = co + (size_t)(r0 + 8) * N + cb;
            if (wantF32) {
                *(float2*)(Cf + o0) = make_float2(y00, y01);
                *(float2*)(Cf + o1) = make_float2(y10, y11);
            } else {
                *(uint32_t*)(Ch + o0) =
                    (uint32_t)__half_as_ushort(__float2half(y00))
                  | ((uint32_t)__half_as_ushort(__float2half(y01)) << 16);
                *(uint32_t*)(Ch + o1) =
                    (uint32_t)__half_as_ushort(__float2half(y10))
                  | ((uint32_t)__half_as_ushort(__float2half(y11)) << 16);
            }
        }
    }
}

// ---------------------------------------------------------------------------
extern "C" void kernel_launch(void* const* d_in, const int* in_sizes, int n_in,
                              void* d_out, int out_size)
{
    (void)in_sizes; (void)n_in; (void)out_size;
    const float* x  = (const float*)d_in[0];
    const float* w1 = (const float*)d_in[1];
    const float* b1 = (const float*)d_in[2];
    const float* w2 = (const float*)d_in[3];
    const float* b2 = (const float*)d_in[4];
    const float* g1w[2] = { (const float*)d_in[5],  (const float*)d_in[9]  };
    const float* g1b[2] = { (const float*)d_in[6],  (const float*)d_in[10] };
    const float* g2w[2] = { (const float*)d_in[7],  (const float*)d_in[11] };
    const float* g2b[2] = { (const float*)d_in[8],  (const float*)d_in[12] };
    float* out = (float*)d_out;

    __half *wh, *aA, *aB;
    cudaGetSymbolAddress((void**)&wh, g_wh);
    cudaGetSymbolAddress((void**)&aA, g_aA);
    cudaGetSymbolAddress((void**)&aB, g_aB);

    const size_t OW1 = 0, OW2 = 8388608;
    const size_t OG[4] = { 16777216, 50331648, 83886080, 117440512 };

    cudaFuncSetAttribute(gemm1p, cudaFuncAttributeMaxDynamicSharedMemorySize, SMEM_SZ);

    auto conv = [&](const float* src, __half* dst, size_t n) {
        int n4 = (int)(n / 4);
        conv_h<<<(n4 + 255) / 256, 256>>>((const float4*)src, dst, n4);
    };

    const int Mg = T_TOK / 4;
    dim3 blk(256);

    // Launch order arranged so the 6th launch (ncu -s 5 -c 1) is gemm1p #1.
    conv(x,      aB,         (size_t)T_TOK * HID);       // 1
    conv(w1,     wh + OW1,   (size_t)IMM * HID);         // 2
    conv(w2,     wh + OW2,   (size_t)HID * IMM);         // 3
    conv(g1w[0], wh + OG[0], (size_t)4 * IMM * HID);     // 4
    conv(g2w[0], wh + OG[1], (size_t)4 * HID * IMM);     // 5

    // 6: x @ w1^T -> actA  [16384, 4096]
    gemm1p<<<dim3(IMM / BN, T_TOK / BM, 1), blk, SMEM_SZ>>>(
        aB, wh + OW1, b1, nullptr, aA, T_TOK, IMM, HID, 0);

    conv(g1w[1], wh + OG[2], (size_t)4 * IMM * HID);     // 7
    conv(g2w[1], wh + OG[3], (size_t)4 * HID * IMM);     // 8

    // actA @ w2^T -> actB  [16384, 2048]
    gemm1p<<<dim3(HID / BN, T_TOK / BM, 1), blk, SMEM_SZ>>>(
        aA, wh + OW2, b2, nullptr, aB, T_TOK, HID, IMM, 0);
    // two grouped-MLP layers
    for (int li = 0; li < 2; li++) {
        gemm1p<<<dim3(IMM / BN, Mg / BM, 4), blk, SMEM_SZ>>>(
            aB, wh + OG[2 * li], g1b[li], nullptr, aA, Mg, IMM, HID, 0);
        int fin = (li == 1);
        gemm1p<<<dim3(HID / BN, Mg / BM, 4), blk, SMEM_SZ>>>(
            aA, wh + OG[2 * li + 1], g2b[li],
            fin ? out : nullptr, aB, Mg, HID, IMM, fin);
    }
}